// round 1
// baseline (speedup 1.0000x reference)
#include <cuda_runtime.h>
#include <math.h>

#define B_  8
#define N_  16384
#define C_  256
#define M_  (B_*N_)      // 131072 rows
#define L_  256          // scan chunk length
#define NC_ (N_/L_)      // 64 chunks

// ---- scratch (static __device__ arrays; no allocation allowed) ----
__device__ float g_k[M_*C_];
__device__ float g_v[M_*C_];
__device__ float g_r[M_*C_];
__device__ float g_y[M_*C_];
__device__ float g_mu[M_];
__device__ float g_rstd[M_];
__device__ float g_e[B_*NC_*C_];
__device__ float g_carry[B_*NC_*C_];

// ============================================================
// 1) LayerNorm row stats: one warp per row (C=256 -> 8 elems/lane)
// ============================================================
__global__ __launch_bounds__(256) void ln_stats_kernel(const float* __restrict__ x) {
    int row  = blockIdx.x * 8 + (threadIdx.x >> 5);
    int lane = threadIdx.x & 31;
    const float* xr = x + (size_t)row * C_;
    float s = 0.f, s2 = 0.f;
    #pragma unroll
    for (int c = lane; c < C_; c += 32) {
        float v = xr[c];
        s  += v;
        s2 += v * v;
    }
    #pragma unroll
    for (int o = 16; o > 0; o >>= 1) {
        s  += __shfl_xor_sync(0xffffffffu, s,  o);
        s2 += __shfl_xor_sync(0xffffffffu, s2, o);
    }
    if (lane == 0) {
        float mu  = s  * (1.0f / C_);
        float var = s2 * (1.0f / C_) - mu * mu;
        g_mu[row]   = mu;
        g_rstd[row] = rsqrtf(var + 1e-5f);
    }
}

// ============================================================
// 2) Fused LN + GEMM producing k, v, sigmoid(r).
//    out[m,d] = sum_c LN(x[m,c]) * W[d,c]
//    Tile: 64x64, 256 threads, 4x4 per thread, BK=16.
//    gridDim = (2048, 12): y-tiles 0-3 -> k, 4-7 -> v, 8-11 -> r.
// ============================================================
__global__ __launch_bounds__(256) void gemm_kvr_kernel(
    const float* __restrict__ x,
    const float* __restrict__ Wk, const float* __restrict__ Wv,
    const float* __restrict__ Wr,
    const float* __restrict__ lnw, const float* __restrict__ lnb)
{
    __shared__ float As[16][65];
    __shared__ float Bs[16][65];

    int mt = blockIdx.x;
    int dt = blockIdx.y;
    int which = dt >> 2;                 // 0:k 1:v 2:r
    int d0 = (dt & 3) * 64;
    const float* W = (which == 0) ? Wk : (which == 1) ? Wv : Wr;
    float* O       = (which == 0) ? g_k : (which == 1) ? g_v : g_r;

    int m0  = mt * 64;
    int tid = threadIdx.x;
    int tx = tid & 15, ty = tid >> 4;

    float acc[4][4];
    #pragma unroll
    for (int i = 0; i < 4; i++)
        #pragma unroll
        for (int j = 0; j < 4; j++) acc[i][j] = 0.f;

    for (int kt = 0; kt < 16; kt++) {
        int k0 = kt * 16;
        #pragma unroll
        for (int i = 0; i < 4; i++) {
            int idx = tid + i * 256;
            int r = idx >> 4, c = idx & 15;
            int row = m0 + r, col = k0 + c;
            float a = x[(size_t)row * C_ + col];
            a = (a - g_mu[row]) * g_rstd[row] * lnw[col] + lnb[col];
            As[c][r] = a;
            Bs[c][r] = W[(size_t)(d0 + r) * C_ + col];
        }
        __syncthreads();
        #pragma unroll
        for (int k = 0; k < 16; k++) {
            float a[4], b[4];
            #pragma unroll
            for (int i = 0; i < 4; i++) a[i] = As[k][ty * 4 + i];
            #pragma unroll
            for (int j = 0; j < 4; j++) b[j] = Bs[k][tx * 4 + j];
            #pragma unroll
            for (int i = 0; i < 4; i++)
                #pragma unroll
                for (int j = 0; j < 4; j++)
                    acc[i][j] = fmaf(a[i], b[j], acc[i][j]);
        }
        __syncthreads();
    }

    bool sig = (which == 2);
    #pragma unroll
    for (int i = 0; i < 4; i++) {
        int row = m0 + ty * 4 + i;
        #pragma unroll
        for (int j = 0; j < 4; j++) {
            float v = acc[i][j];
            if (sig) v = 1.0f / (1.0f + expf(-v));
            O[(size_t)row * C_ + d0 + tx * 4 + j] = v;
        }
    }
}

// ============================================================
// 3) Plain GEMM for the output projection: out = y @ W_o^T
//    gridDim = (2048, 4)
// ============================================================
__global__ __launch_bounds__(256) void gemm_out_kernel(
    const float* __restrict__ Wo, float* __restrict__ out)
{
    __shared__ float As[16][65];
    __shared__ float Bs[16][65];

    int m0 = blockIdx.x * 64;
    int d0 = blockIdx.y * 64;
    int tid = threadIdx.x;
    int tx = tid & 15, ty = tid >> 4;

    float acc[4][4];
    #pragma unroll
    for (int i = 0; i < 4; i++)
        #pragma unroll
        for (int j = 0; j < 4; j++) acc[i][j] = 0.f;

    for (int kt = 0; kt < 16; kt++) {
        int k0 = kt * 16;
        #pragma unroll
        for (int i = 0; i < 4; i++) {
            int idx = tid + i * 256;
            int r = idx >> 4, c = idx & 15;
            As[c][r] = g_y[(size_t)(m0 + r) * C_ + k0 + c];
            Bs[c][r] = Wo[(size_t)(d0 + r) * C_ + k0 + c];
        }
        __syncthreads();
        #pragma unroll
        for (int k = 0; k < 16; k++) {
            float a[4], b[4];
            #pragma unroll
            for (int i = 0; i < 4; i++) a[i] = As[k][ty * 4 + i];
            #pragma unroll
            for (int j = 0; j < 4; j++) b[j] = Bs[k][tx * 4 + j];
            #pragma unroll
            for (int i = 0; i < 4; i++)
                #pragma unroll
                for (int j = 0; j < 4; j++)
                    acc[i][j] = fmaf(a[i], b[j], acc[i][j]);
        }
        __syncthreads();
    }

    #pragma unroll
    for (int i = 0; i < 4; i++) {
        int row = m0 + ty * 4 + i;
        #pragma unroll
        for (int j = 0; j < 4; j++)
            out[(size_t)row * C_ + d0 + tx * 4 + j] = acc[i][j];
    }
}

// ============================================================
// 4) Scan pass 1: local chunk scans, keep end value only.
//    grid (NC_, B_), 256 threads = one channel each.
// ============================================================
__global__ __launch_bounds__(256) void scan1_kernel(const float* __restrict__ td) {
    int b = blockIdx.y, j = blockIdx.x, c = threadIdx.x;
    float d = expf(-fmaxf(td[c], 0.f));
    const float* kp = g_k + ((size_t)(b * N_ + j * L_)) * C_ + c;
    float s = 0.f;
    #pragma unroll 8
    for (int i = 0; i < L_; i++)
        s = fmaf(s, d, kp[(size_t)i * C_]);
    g_e[(b * NC_ + j) * C_ + c] = s;
}

// ============================================================
// 5) Carry propagation across chunks (tiny).
//    grid (B_), 256 threads.
// ============================================================
__global__ __launch_bounds__(256) void scan_carry_kernel(const float* __restrict__ td) {
    int b = blockIdx.x, c = threadIdx.x;
    float r  = fmaxf(td[c], 0.f);
    float dL = expf(-r * (float)L_);   // d^L
    float cy = 0.f;
    for (int j = 0; j < NC_; j++) {
        g_carry[(b * NC_ + j) * C_ + c] = cy;
        cy = fmaf(dL, cy, g_e[(b * NC_ + j) * C_ + c]);
    }
}

// ============================================================
// 6) Scan pass 2 with injected carry, fused with y = r*(state+v).
//    grid (NC_, B_), 256 threads.
// ============================================================
__global__ __launch_bounds__(256) void scan2_kernel(const float* __restrict__ td) {
    int b = blockIdx.y, j = blockIdx.x, c = threadIdx.x;
    float d = expf(-fmaxf(td[c], 0.f));
    size_t base = ((size_t)(b * N_ + j * L_)) * C_ + c;
    float s = g_carry[(b * NC_ + j) * C_ + c];
    #pragma unroll 8
    for (int i = 0; i < L_; i++) {
        size_t off = base + (size_t)i * C_;
        s = fmaf(s, d, g_k[off]);
        g_y[off] = g_r[off] * (s + g_v[off]);
    }
}

// ============================================================
// launch
// ============================================================
extern "C" void kernel_launch(void* const* d_in, const int* in_sizes, int n_in,
                              void* d_out, int out_size) {
    const float* x   = (const float*)d_in[0];
    const float* td  = (const float*)d_in[1];
    const float* Wk  = (const float*)d_in[2];
    const float* Wv  = (const float*)d_in[3];
    const float* Wr  = (const float*)d_in[4];
    const float* Wo  = (const float*)d_in[5];
    const float* lnw = (const float*)d_in[6];
    const float* lnb = (const float*)d_in[7];
    float* out = (float*)d_out;

    ln_stats_kernel<<<M_ / 8, 256>>>(x);
    gemm_kvr_kernel<<<dim3(M_ / 64, 12), 256>>>(x, Wk, Wv, Wr, lnw, lnb);
    scan1_kernel<<<dim3(NC_, B_), 256>>>(td);
    scan_carry_kernel<<<B_, 256>>>(td);
    scan2_kernel<<<dim3(NC_, B_), 256>>>(td);
    gemm_out_kernel<<<dim3(M_ / 64, 4), 256>>>(Wo, out);
}

// round 2
// speedup vs baseline: 2.0277x; 2.0277x over previous
#include <cuda_runtime.h>
#include <cuda_bf16.h>
#include <math.h>
#include <stdint.h>

#define B_  8
#define N_  16384
#define C_  256
#define M_  (B_*N_)      // 131072 rows
#define MC_ ((size_t)M_*C_)
#define L_  256          // scan chunk length
#define NC_ (N_/L_)      // 64 chunks

// GEMM tiling
#define BM 128
#define BN 64
#define KC 32
#define SAS 40           // smem row stride (halves): conflict-free for ldmatrix
#define SBS 40

// ---- scratch (static __device__ arrays; no allocation allowed) ----
__device__ float          g_kvr[3*MC_];      // k, v, r  (fp32 for scan precision)
__device__ __nv_bfloat16  g_xh[MC_], g_xl[MC_];   // LN(x) split
__device__ __nv_bfloat16  g_yh[MC_], g_yl[MC_];   // y split
__device__ __nv_bfloat16  g_Wh[3*C_*C_], g_Wl[3*C_*C_];   // Wk,Wv,Wr split
__device__ __nv_bfloat16  g_Woh[C_*C_], g_Wol[C_*C_];     // Wo split
__device__ float          g_e[B_*NC_*C_];
__device__ float          g_carry[B_*NC_*C_];

// ============================================================
// helpers
// ============================================================
__device__ __forceinline__ uint32_t smem_u32(const void* p) {
    return (uint32_t)__cvta_generic_to_shared(p);
}
__device__ __forceinline__ void ldm_x4(uint32_t* r, uint32_t addr) {
    asm volatile("ldmatrix.sync.aligned.m8n8.x4.shared.b16 {%0,%1,%2,%3}, [%4];"
                 : "=r"(r[0]), "=r"(r[1]), "=r"(r[2]), "=r"(r[3]) : "r"(addr));
}
__device__ __forceinline__ void mma16816(float* c, const uint32_t* a,
                                         uint32_t b0, uint32_t b1) {
    asm volatile(
        "mma.sync.aligned.m16n8k16.row.col.f32.bf16.bf16.f32 "
        "{%0,%1,%2,%3}, {%4,%5,%6,%7}, {%8,%9}, {%0,%1,%2,%3};"
        : "+f"(c[0]), "+f"(c[1]), "+f"(c[2]), "+f"(c[3])
        : "r"(a[0]), "r"(a[1]), "r"(a[2]), "r"(a[3]), "r"(b0), "r"(b1));
}

// ============================================================
// 1) LayerNorm + bf16 hi/lo split.  One warp per row, 8 rows/block.
// ============================================================
__global__ __launch_bounds__(256) void ln_split_kernel(
    const float* __restrict__ x,
    const float* __restrict__ lnw, const float* __restrict__ lnb)
{
    int row  = blockIdx.x * 8 + (threadIdx.x >> 5);
    int lane = threadIdx.x & 31;
    int c0   = lane * 8;
    const float4* xr = reinterpret_cast<const float4*>(x + (size_t)row * C_ + c0);
    float4 f0 = xr[0], f1 = xr[1];
    float v[8] = {f0.x, f0.y, f0.z, f0.w, f1.x, f1.y, f1.z, f1.w};

    float s = 0.f, s2 = 0.f;
    #pragma unroll
    for (int j = 0; j < 8; j++) { s += v[j]; s2 += v[j] * v[j]; }
    #pragma unroll
    for (int o = 16; o > 0; o >>= 1) {
        s  += __shfl_xor_sync(0xffffffffu, s,  o);
        s2 += __shfl_xor_sync(0xffffffffu, s2, o);
    }
    float mu   = s * (1.0f / C_);
    float var  = s2 * (1.0f / C_) - mu * mu;
    float rstd = rsqrtf(var + 1e-5f);

    union { __nv_bfloat16 h[8]; uint4 u; } hi, lo;
    #pragma unroll
    for (int j = 0; j < 8; j++) {
        float xn = (v[j] - mu) * rstd * lnw[c0 + j] + lnb[c0 + j];
        __nv_bfloat16 h = __float2bfloat16(xn);
        hi.h[j] = h;
        lo.h[j] = __float2bfloat16(xn - __bfloat162float(h));
    }
    size_t off = ((size_t)row * C_ + c0);
    *reinterpret_cast<uint4*>(&g_xh[off]) = hi.u;
    *reinterpret_cast<uint4*>(&g_xl[off]) = lo.u;
}

// ============================================================
// 2) Split the four weight matrices into bf16 hi/lo.
// ============================================================
__global__ __launch_bounds__(256) void wsplit_kernel(
    const float* __restrict__ Wk, const float* __restrict__ Wv,
    const float* __restrict__ Wr, const float* __restrict__ Wo)
{
    int idx = blockIdx.x * 256 + threadIdx.x;   // 0 .. 4*65536-1
    int mat = idx >> 16, rem = idx & 65535;
    float val = (mat == 0) ? Wk[rem] : (mat == 1) ? Wv[rem]
              : (mat == 2) ? Wr[rem] : Wo[rem];
    __nv_bfloat16 h = __float2bfloat16(val);
    __nv_bfloat16 l = __float2bfloat16(val - __bfloat162float(h));
    if (mat < 3) { g_Wh[idx] = h; g_Wl[idx] = l; }
    else         { g_Woh[rem] = h; g_Wol[rem] = l; }
}

// ============================================================
// 3) bf16-split tensor-core GEMM:  O[m,d] = sum_c A[m,c]*W[d,c]
//    = Ah*Wh + Al*Wh + Ah*Wl.   Block tile 128x64, 8 warps (4x2),
//    warp tile 32x32 = 2x4 m16n8k16 tiles.  grid (M/128, C/64, nmat)
// ============================================================
__global__ __launch_bounds__(256) void mma_gemm_kernel(
    const __nv_bfloat16* __restrict__ Ah, const __nv_bfloat16* __restrict__ Al,
    const __nv_bfloat16* __restrict__ Wh, const __nv_bfloat16* __restrict__ Wl,
    float* __restrict__ O, int sig_z)
{
    __shared__ __nv_bfloat16 sAh[BM*SAS], sAl[BM*SAS];
    __shared__ __nv_bfloat16 sBh[BN*SBS], sBl[BN*SBS];

    int z = blockIdx.z;
    const __nv_bfloat16* wh = Wh + (size_t)z * C_ * C_;
    const __nv_bfloat16* wl = Wl + (size_t)z * C_ * C_;
    float* out = O + (size_t)z * MC_;
    size_t m0 = (size_t)blockIdx.x * BM;
    int n0 = blockIdx.y * BN;

    int tid = threadIdx.x;
    int warp = tid >> 5, lane = tid & 31;
    int wm = (warp & 3) * 32;
    int wn = (warp >> 2) * 32;
    int gID = lane >> 2, tig = lane & 3;

    float acc[2][4][4];
    #pragma unroll
    for (int i = 0; i < 2; i++)
        #pragma unroll
        for (int j = 0; j < 4; j++)
            #pragma unroll
            for (int q = 0; q < 4; q++) acc[i][j][q] = 0.f;

    // ldmatrix lane-address components (constant over k loop)
    int arow = (lane & 15);              // A: lanes 0-15 rows, 16-31 rows (col+8)
    int acolo = (lane >> 4) << 3;
    int q4 = lane >> 3;
    int brow_in = (lane & 7) + ((q4 >> 1) << 3);
    int bcolo = (q4 & 1) << 3;

    for (int kc = 0; kc < C_ / KC; kc++) {
        int k0 = kc * KC;
        __syncthreads();
        // load A tile: BM x KC halves (hi+lo), 8 halves per uint4
        #pragma unroll
        for (int i = tid; i < BM * KC / 8; i += 256) {
            int r = i >> 2, cv = i & 3;
            size_t goff = (m0 + r) * C_ + k0 + cv * 8;
            *reinterpret_cast<uint4*>(&sAh[r * SAS + cv * 8]) =
                *reinterpret_cast<const uint4*>(Ah + goff);
            *reinterpret_cast<uint4*>(&sAl[r * SAS + cv * 8]) =
                *reinterpret_cast<const uint4*>(Al + goff);
        }
        // load B tile: BN x KC halves (hi+lo)
        #pragma unroll
        for (int i = tid; i < BN * KC / 8; i += 256) {
            int r = i >> 2, cv = i & 3;
            size_t goff = (size_t)(n0 + r) * C_ + k0 + cv * 8;
            *reinterpret_cast<uint4*>(&sBh[r * SBS + cv * 8]) =
                *reinterpret_cast<const uint4*>(wh + goff);
            *reinterpret_cast<uint4*>(&sBl[r * SBS + cv * 8]) =
                *reinterpret_cast<const uint4*>(wl + goff);
        }
        __syncthreads();

        #pragma unroll
        for (int ks = 0; ks < KC / 16; ks++) {
            int kk = ks * 16;
            uint32_t ah[2][4], al[2][4], bh[2][4], bl[2][4];
            #pragma unroll
            for (int i = 0; i < 2; i++) {
                int ro = (wm + i * 16 + arow) * SAS + kk + acolo;
                ldm_x4(ah[i], smem_u32(&sAh[ro]));
                ldm_x4(al[i], smem_u32(&sAl[ro]));
            }
            #pragma unroll
            for (int p = 0; p < 2; p++) {
                int ro = (wn + p * 16 + brow_in) * SBS + kk + bcolo;
                ldm_x4(bh[p], smem_u32(&sBh[ro]));
                ldm_x4(bl[p], smem_u32(&sBl[ro]));
            }
            #pragma unroll
            for (int i = 0; i < 2; i++)
                #pragma unroll
                for (int j = 0; j < 4; j++) {
                    int p = j >> 1, o = (j & 1) * 2;
                    mma16816(acc[i][j], ah[i], bh[p][o], bh[p][o + 1]);
                    mma16816(acc[i][j], al[i], bh[p][o], bh[p][o + 1]);
                    mma16816(acc[i][j], ah[i], bl[p][o], bl[p][o + 1]);
                }
        }
    }

    bool sig = (z == sig_z);
    #pragma unroll
    for (int i = 0; i < 2; i++) {
        size_t row0 = m0 + wm + i * 16 + gID;
        #pragma unroll
        for (int j = 0; j < 4; j++) {
            int col = n0 + wn + j * 8 + tig * 2;
            float v0 = acc[i][j][0], v1 = acc[i][j][1];
            float v2 = acc[i][j][2], v3 = acc[i][j][3];
            if (sig) {
                v0 = 1.0f / (1.0f + expf(-v0));
                v1 = 1.0f / (1.0f + expf(-v1));
                v2 = 1.0f / (1.0f + expf(-v2));
                v3 = 1.0f / (1.0f + expf(-v3));
            }
            *reinterpret_cast<float2*>(&out[row0 * C_ + col])       = make_float2(v0, v1);
            *reinterpret_cast<float2*>(&out[(row0 + 8) * C_ + col]) = make_float2(v2, v3);
        }
    }
}

// ============================================================
// 4) Scan pass 1: local chunk scans, keep end value only.
// ============================================================
__global__ __launch_bounds__(256) void scan1_kernel(const float* __restrict__ td) {
    int b = blockIdx.y, j = blockIdx.x, c = threadIdx.x;
    float d = expf(-fmaxf(td[c], 0.f));
    const float* kp = g_kvr + ((size_t)(b * N_ + j * L_)) * C_ + c;
    float s = 0.f;
    #pragma unroll 8
    for (int i = 0; i < L_; i++)
        s = fmaf(s, d, kp[(size_t)i * C_]);
    g_e[(b * NC_ + j) * C_ + c] = s;
}

// ============================================================
// 5) Carry propagation across chunks (tiny).
// ============================================================
__global__ __launch_bounds__(256) void scan_carry_kernel(const float* __restrict__ td) {
    int b = blockIdx.x, c = threadIdx.x;
    float r  = fmaxf(td[c], 0.f);
    float dL = expf(-r * (float)L_);
    float cy = 0.f;
    for (int j = 0; j < NC_; j++) {
        g_carry[(b * NC_ + j) * C_ + c] = cy;
        cy = fmaf(dL, cy, g_e[(b * NC_ + j) * C_ + c]);
    }
}

// ============================================================
// 6) Scan pass 2 + y = r*(state+v), emitted as bf16 hi/lo.
// ============================================================
__global__ __launch_bounds__(256) void scan2_kernel(const float* __restrict__ td) {
    int b = blockIdx.y, j = blockIdx.x, c = threadIdx.x;
    float d = expf(-fmaxf(td[c], 0.f));
    size_t base = ((size_t)(b * N_ + j * L_)) * C_ + c;
    float s = g_carry[(b * NC_ + j) * C_ + c];
    #pragma unroll 4
    for (int i = 0; i < L_; i++) {
        size_t off = base + (size_t)i * C_;
        s = fmaf(s, d, g_kvr[off]);
        float y = g_kvr[2 * MC_ + off] * (s + g_kvr[MC_ + off]);
        __nv_bfloat16 h = __float2bfloat16(y);
        g_yh[off] = h;
        g_yl[off] = __float2bfloat16(y - __bfloat162float(h));
    }
}

// ============================================================
// launch
// ============================================================
extern "C" void kernel_launch(void* const* d_in, const int* in_sizes, int n_in,
                              void* d_out, int out_size) {
    const float* x   = (const float*)d_in[0];
    const float* td  = (const float*)d_in[1];
    const float* Wk  = (const float*)d_in[2];
    const float* Wv  = (const float*)d_in[3];
    const float* Wr  = (const float*)d_in[4];
    const float* Wo  = (const float*)d_in[5];
    const float* Wo_ = Wo;
    const float* lnw = (const float*)d_in[6];
    const float* lnb = (const float*)d_in[7];
    float* out = (float*)d_out;

    __nv_bfloat16 *xh, *xl, *yh, *yl, *Wh, *Wl, *Woh, *Wol;
    cudaGetSymbolAddress((void**)&xh,  g_xh);
    cudaGetSymbolAddress((void**)&xl,  g_xl);
    cudaGetSymbolAddress((void**)&yh,  g_yh);
    cudaGetSymbolAddress((void**)&yl,  g_yl);
    cudaGetSymbolAddress((void**)&Wh,  g_Wh);
    cudaGetSymbolAddress((void**)&Wl,  g_Wl);
    cudaGetSymbolAddress((void**)&Woh, g_Woh);
    cudaGetSymbolAddress((void**)&Wol, g_Wol);
    float* kvr;
    cudaGetSymbolAddress((void**)&kvr, g_kvr);

    ln_split_kernel<<<M_ / 8, 256>>>(x, lnw, lnb);
    wsplit_kernel<<<1024, 256>>>(Wk, Wv, Wr, Wo_);
    mma_gemm_kernel<<<dim3(M_ / BM, C_ / BN, 3), 256>>>(xh, xl, Wh, Wl, kvr, 2);
    scan1_kernel<<<dim3(NC_, B_), 256>>>(td);
    scan_carry_kernel<<<B_, 256>>>(td);
    scan2_kernel<<<dim3(NC_, B_), 256>>>(td);
    mma_gemm_kernel<<<dim3(M_ / BM, C_ / BN, 1), 256>>>(yh, yl, Woh, Wol, out, -1);
}

// round 4
// speedup vs baseline: 3.6421x; 1.7962x over previous
#include <cuda_runtime.h>
#include <cuda_bf16.h>
#include <math.h>
#include <stdint.h>

#define B_  8
#define N_  16384
#define C_  256
#define M_  (B_*N_)      // 131072 rows
#define MC_ ((size_t)M_*C_)
#define L_  256          // scan chunk length
#define NC_ (N_/L_)      // 64 chunks

// ---- GEMM tiling ----
#define BM 128
#define BN 64
#define KCH 64                 // K chunk (bf16 elems)
#define NKC (C_/KCH)           // 4 chunks
#define SAS 72                 // smem row stride in halves (144B = 9*16B)
#define A_HALF_B (BM*SAS*2)    // 18432 bytes per A half-matrix
#define B_HALF_B (BN*SAS*2)    // 9216
#define STAGE_B (2*A_HALF_B + 2*B_HALF_B)   // 55296
#define SMEM_REQ (2*STAGE_B)                // 110592

// ---- scratch ----
__device__ float          g_kvr[3*MC_];
__device__ __nv_bfloat16  g_xh[MC_], g_xl[MC_];
__device__ __nv_bfloat16  g_yh[MC_], g_yl[MC_];
__device__ __nv_bfloat16  g_Wh[3*C_*C_], g_Wl[3*C_*C_];
__device__ __nv_bfloat16  g_Woh[C_*C_], g_Wol[C_*C_];
__device__ float          g_e[B_*NC_*C_];
__device__ float          g_carry[B_*NC_*C_];

// ============================================================
// helpers
// ============================================================
__device__ __forceinline__ uint32_t smem_u32(const void* p) {
    return (uint32_t)__cvta_generic_to_shared(p);
}
__device__ __forceinline__ void ldm_x4(uint32_t* r, uint32_t addr) {
    asm volatile("ldmatrix.sync.aligned.m8n8.x4.shared.b16 {%0,%1,%2,%3}, [%4];"
                 : "=r"(r[0]), "=r"(r[1]), "=r"(r[2]), "=r"(r[3]) : "r"(addr));
}
__device__ __forceinline__ void mma16816(float* c, const uint32_t* a,
                                         uint32_t b0, uint32_t b1) {
    asm volatile(
        "mma.sync.aligned.m16n8k16.row.col.f32.bf16.bf16.f32 "
        "{%0,%1,%2,%3}, {%4,%5,%6,%7}, {%8,%9}, {%0,%1,%2,%3};"
        : "+f"(c[0]), "+f"(c[1]), "+f"(c[2]), "+f"(c[3])
        : "r"(a[0]), "r"(a[1]), "r"(a[2]), "r"(a[3]), "r"(b0), "r"(b1));
}
__device__ __forceinline__ void cp16(uint32_t sm, const void* g) {
    asm volatile("cp.async.cg.shared.global [%0], [%1], 16;" :: "r"(sm), "l"(g));
}
__device__ __forceinline__ void cp_commit() {
    asm volatile("cp.async.commit_group;");
}
template <int N>
__device__ __forceinline__ void cp_wait() {
    asm volatile("cp.async.wait_group %0;" :: "n"(N));
}

// ============================================================
// 1) LayerNorm + bf16 hi/lo split
// ============================================================
__global__ __launch_bounds__(256) void ln_split_kernel(
    const float* __restrict__ x,
    const float* __restrict__ lnw, const float* __restrict__ lnb)
{
    int row  = blockIdx.x * 8 + (threadIdx.x >> 5);
    int lane = threadIdx.x & 31;
    int c0   = lane * 8;
    const float4* xr = reinterpret_cast<const float4*>(x + (size_t)row * C_ + c0);
    float4 f0 = xr[0], f1 = xr[1];
    float v[8] = {f0.x, f0.y, f0.z, f0.w, f1.x, f1.y, f1.z, f1.w};

    float s = 0.f, s2 = 0.f;
    #pragma unroll
    for (int j = 0; j < 8; j++) { s += v[j]; s2 += v[j] * v[j]; }
    #pragma unroll
    for (int o = 16; o > 0; o >>= 1) {
        s  += __shfl_xor_sync(0xffffffffu, s,  o);
        s2 += __shfl_xor_sync(0xffffffffu, s2, o);
    }
    float mu   = s * (1.0f / C_);
    float var  = s2 * (1.0f / C_) - mu * mu;
    float rstd = rsqrtf(var + 1e-5f);

    union { __nv_bfloat16 h[8]; uint4 u; } hi, lo;
    #pragma unroll
    for (int j = 0; j < 8; j++) {
        float xn = (v[j] - mu) * rstd * lnw[c0 + j] + lnb[c0 + j];
        __nv_bfloat16 h = __float2bfloat16(xn);
        hi.h[j] = h;
        lo.h[j] = __float2bfloat16(xn - __bfloat162float(h));
    }
    size_t off = ((size_t)row * C_ + c0);
    *reinterpret_cast<uint4*>(&g_xh[off]) = hi.u;
    *reinterpret_cast<uint4*>(&g_xl[off]) = lo.u;
}

// ============================================================
// 2) Weight split
// ============================================================
__global__ __launch_bounds__(256) void wsplit_kernel(
    const float* __restrict__ Wk, const float* __restrict__ Wv,
    const float* __restrict__ Wr, const float* __restrict__ Wo)
{
    int idx = blockIdx.x * 256 + threadIdx.x;
    int mat = idx >> 16, rem = idx & 65535;
    float val = (mat == 0) ? Wk[rem] : (mat == 1) ? Wv[rem]
              : (mat == 2) ? Wr[rem] : Wo[rem];
    __nv_bfloat16 h = __float2bfloat16(val);
    __nv_bfloat16 l = __float2bfloat16(val - __bfloat162float(h));
    if (mat < 3) { g_Wh[idx] = h; g_Wl[idx] = l; }
    else         { g_Woh[rem] = h; g_Wol[rem] = l; }
}

// ============================================================
// 3) split-bf16 mma.sync GEMM, cp.async double-buffered.
//    Block 128x64 over K=256, 8 warps (4m x 2n), warp 32x32.
//    grid: x = n_tiles*nz (fast, L2 A-reuse), y = M/BM
// ============================================================
__global__ void __launch_bounds__(256, 2) mma_gemm_kernel(
    const __nv_bfloat16* __restrict__ Ah, const __nv_bfloat16* __restrict__ Al,
    const __nv_bfloat16* __restrict__ Wh, const __nv_bfloat16* __restrict__ Wl,
    float* __restrict__ O, int nz, int sig_z)
{
    extern __shared__ __nv_bfloat16 sm[];
    uint32_t sbase = smem_u32(sm);

    int zc = blockIdx.x;
    int z  = zc % nz;
    int ny = zc / nz;
    size_t m0 = (size_t)blockIdx.y * BM;
    int n0 = ny * BN;
    const __nv_bfloat16* wh = Wh + (size_t)z * C_ * C_;
    const __nv_bfloat16* wl = Wl + (size_t)z * C_ * C_;
    float* out = O + (size_t)z * MC_;

    int tid = threadIdx.x;
    int warp = tid >> 5, lane = tid & 31;
    int wm = (warp & 3) * 32;
    int wn = (warp >> 2) * 32;
    int gID = lane >> 2, tig = lane & 3;

    float acc[2][4][4];
    #pragma unroll
    for (int i = 0; i < 2; i++)
        #pragma unroll
        for (int j = 0; j < 4; j++)
            #pragma unroll
            for (int q = 0; q < 4; q++) acc[i][j][q] = 0.f;

    int arow  = lane & 15;
    int acolo = (lane >> 4) << 3;
    int q4 = lane >> 3;
    int brow_in = (lane & 7) + ((q4 >> 1) << 3);
    int bcolo = (q4 & 1) << 3;

    // stage byte offsets
    auto load_chunk = [&](int kc, int stg) {
        uint32_t base = sbase + stg * STAGE_B;
        int k0 = kc * KCH;
        #pragma unroll
        for (int it = 0; it < 4; it++) {            // A: 1024 vec16 per half
            int v = it * 256 + tid;
            int r = v >> 3, cv = v & 7;
            uint32_t so = r * (SAS * 2) + cv * 16;
            size_t g = (m0 + r) * C_ + k0 + cv * 8;
            cp16(base + so,            Ah + g);
            cp16(base + A_HALF_B + so, Al + g);
        }
        #pragma unroll
        for (int it = 0; it < 2; it++) {            // B: 512 vec16 per half
            int v = it * 256 + tid;
            int r = v >> 3, cv = v & 7;
            uint32_t so = r * (SAS * 2) + cv * 16;
            size_t g = (size_t)(n0 + r) * C_ + k0 + cv * 8;
            cp16(base + 2 * A_HALF_B + so,            wh + g);
            cp16(base + 2 * A_HALF_B + B_HALF_B + so, wl + g);
        }
        cp_commit();
    };

    load_chunk(0, 0);

    for (int kc = 0; kc < NKC; kc++) {
        cp_wait<0>();
        __syncthreads();
        if (kc + 1 < NKC) load_chunk(kc + 1, (kc + 1) & 1);

        uint32_t base = sbase + (kc & 1) * STAGE_B;
        uint32_t aB = base, alB = base + A_HALF_B;
        uint32_t bB = base + 2 * A_HALF_B, blB = bB + B_HALF_B;

        #pragma unroll
        for (int ks = 0; ks < KCH / 16; ks++) {
            int kk = ks * 16;
            uint32_t ah[2][4], al[2][4], bh[2][4], bl[2][4];
            #pragma unroll
            for (int i = 0; i < 2; i++) {
                uint32_t ro = (wm + i * 16 + arow) * (SAS * 2) + (kk + acolo) * 2;
                ldm_x4(ah[i], aB + ro);
                ldm_x4(al[i], alB + ro);
            }
            #pragma unroll
            for (int p = 0; p < 2; p++) {
                uint32_t ro = (wn + p * 16 + brow_in) * (SAS * 2) + (kk + bcolo) * 2;
                ldm_x4(bh[p], bB + ro);
                ldm_x4(bl[p], blB + ro);
            }
            #pragma unroll
            for (int i = 0; i < 2; i++)
                #pragma unroll
                for (int j = 0; j < 4; j++) {
                    int p = j >> 1, o = (j & 1) * 2;
                    mma16816(acc[i][j], ah[i], bh[p][o], bh[p][o + 1]);
                    mma16816(acc[i][j], al[i], bh[p][o], bh[p][o + 1]);
                    mma16816(acc[i][j], ah[i], bl[p][o], bl[p][o + 1]);
                }
        }
    }

    bool sig = (z == sig_z);
    #pragma unroll
    for (int i = 0; i < 2; i++) {
        size_t row0 = m0 + wm + i * 16 + gID;
        #pragma unroll
        for (int j = 0; j < 4; j++) {
            int col = n0 + wn + j * 8 + tig * 2;
            float v0 = acc[i][j][0], v1 = acc[i][j][1];
            float v2 = acc[i][j][2], v3 = acc[i][j][3];
            if (sig) {
                v0 = 1.0f / (1.0f + __expf(-v0));
                v1 = 1.0f / (1.0f + __expf(-v1));
                v2 = 1.0f / (1.0f + __expf(-v2));
                v3 = 1.0f / (1.0f + __expf(-v3));
            }
            *reinterpret_cast<float2*>(&out[row0 * C_ + col])       = make_float2(v0, v1);
            *reinterpret_cast<float2*>(&out[(row0 + 8) * C_ + col]) = make_float2(v2, v3);
        }
    }
}

// ============================================================
// 4) Scan pass 1 (float4)
// ============================================================
__global__ __launch_bounds__(256) void scan1_kernel(const float* __restrict__ td) {
    int sub = threadIdx.x >> 6, t = threadIdx.x & 63;
    int j = blockIdx.x * 4 + sub, b = blockIdx.y;
    int c0 = t * 4;
    float4 tdv = *reinterpret_cast<const float4*>(td + c0);
    float dx = __expf(-fmaxf(tdv.x, 0.f)), dy = __expf(-fmaxf(tdv.y, 0.f));
    float dz = __expf(-fmaxf(tdv.z, 0.f)), dw = __expf(-fmaxf(tdv.w, 0.f));
    const float4* kp = reinterpret_cast<const float4*>(
        g_kvr + ((size_t)(b * N_ + j * L_)) * C_) + t;
    float4 s = make_float4(0.f, 0.f, 0.f, 0.f);
    #pragma unroll 8
    for (int i = 0; i < L_; i++) {
        float4 kv = kp[(size_t)i * (C_ / 4)];
        s.x = fmaf(s.x, dx, kv.x); s.y = fmaf(s.y, dy, kv.y);
        s.z = fmaf(s.z, dz, kv.z); s.w = fmaf(s.w, dw, kv.w);
    }
    reinterpret_cast<float4*>(g_e + (b * NC_ + j) * C_)[t] = s;
}

// ============================================================
// 5) Carry propagation, batched independent loads
// ============================================================
__global__ __launch_bounds__(256) void scan_carry_kernel(const float* __restrict__ td) {
    int b = blockIdx.x, c = threadIdx.x;
    float r  = fmaxf(td[c], 0.f);
    float dL = __expf(-r * (float)L_);
    float cy = 0.f;
    for (int jb = 0; jb < NC_; jb += 8) {
        float e[8];
        #pragma unroll
        for (int u = 0; u < 8; u++) e[u] = g_e[(b * NC_ + jb + u) * C_ + c];
        #pragma unroll
        for (int u = 0; u < 8; u++) {
            g_carry[(b * NC_ + jb + u) * C_ + c] = cy;
            cy = fmaf(dL, cy, e[u]);
        }
    }
}

// ============================================================
// 6) Scan pass 2 (float4) + y = r*(s+v) -> bf16 hi/lo
// ============================================================
__global__ __launch_bounds__(256) void scan2_kernel(const float* __restrict__ td) {
    int sub = threadIdx.x >> 6, t = threadIdx.x & 63;
    int j = blockIdx.x * 4 + sub, b = blockIdx.y;
    int c0 = t * 4;
    float4 tdv = *reinterpret_cast<const float4*>(td + c0);
    float dx = __expf(-fmaxf(tdv.x, 0.f)), dy = __expf(-fmaxf(tdv.y, 0.f));
    float dz = __expf(-fmaxf(tdv.z, 0.f)), dw = __expf(-fmaxf(tdv.w, 0.f));
    size_t base = ((size_t)(b * N_ + j * L_)) * C_ + c0;
    float4 s = reinterpret_cast<const float4*>(g_carry + (b * NC_ + j) * C_)[t];
    #pragma unroll 4
    for (int i = 0; i < L_; i++) {
        size_t off = base + (size_t)i * C_;
        float4 kv = *reinterpret_cast<const float4*>(g_kvr + off);
        float4 vv = *reinterpret_cast<const float4*>(g_kvr + MC_ + off);
        float4 rv = *reinterpret_cast<const float4*>(g_kvr + 2 * MC_ + off);
        s.x = fmaf(s.x, dx, kv.x); s.y = fmaf(s.y, dy, kv.y);
        s.z = fmaf(s.z, dz, kv.z); s.w = fmaf(s.w, dw, kv.w);
        float y0 = rv.x * (s.x + vv.x), y1 = rv.y * (s.y + vv.y);
        float y2 = rv.z * (s.z + vv.z), y3 = rv.w * (s.w + vv.w);
        union { __nv_bfloat16 h[4]; uint2 u; } H, Lo;
        H.h[0] = __float2bfloat16(y0); H.h[1] = __float2bfloat16(y1);
        H.h[2] = __float2bfloat16(y2); H.h[3] = __float2bfloat16(y3);
        Lo.h[0] = __float2bfloat16(y0 - __bfloat162float(H.h[0]));
        Lo.h[1] = __float2bfloat16(y1 - __bfloat162float(H.h[1]));
        Lo.h[2] = __float2bfloat16(y2 - __bfloat162float(H.h[2]));
        Lo.h[3] = __float2bfloat16(y3 - __bfloat162float(H.h[3]));
        *reinterpret_cast<uint2*>(&g_yh[off]) = H.u;
        *reinterpret_cast<uint2*>(&g_yl[off]) = Lo.u;
    }
}

// ============================================================
// launch
// ============================================================
extern "C" void kernel_launch(void* const* d_in, const int* in_sizes, int n_in,
                              void* d_out, int out_size) {
    const float* x   = (const float*)d_in[0];
    const float* td  = (const float*)d_in[1];
    const float* Wk  = (const float*)d_in[2];
    const float* Wv  = (const float*)d_in[3];
    const float* Wr  = (const float*)d_in[4];
    const float* Wo  = (const float*)d_in[5];
    const float* lnw = (const float*)d_in[6];
    const float* lnb = (const float*)d_in[7];
    float* out = (float*)d_out;

    __nv_bfloat16 *xh, *xl, *yh, *yl, *Wh, *Wl, *Woh, *Wol;
    cudaGetSymbolAddress((void**)&xh,  g_xh);
    cudaGetSymbolAddress((void**)&xl,  g_xl);
    cudaGetSymbolAddress((void**)&yh,  g_yh);
    cudaGetSymbolAddress((void**)&yl,  g_yl);
    cudaGetSymbolAddress((void**)&Wh,  g_Wh);
    cudaGetSymbolAddress((void**)&Wl,  g_Wl);
    cudaGetSymbolAddress((void**)&Woh, g_Woh);
    cudaGetSymbolAddress((void**)&Wol, g_Wol);
    float* kvr;
    cudaGetSymbolAddress((void**)&kvr, g_kvr);

    cudaFuncSetAttribute(mma_gemm_kernel,
                         cudaFuncAttributeMaxDynamicSharedMemorySize, SMEM_REQ);

    ln_split_kernel<<<M_ / 8, 256>>>(x, lnw, lnb);
    wsplit_kernel<<<1024, 256>>>(Wk, Wv, Wr, Wo);
    mma_gemm_kernel<<<dim3((C_ / BN) * 3, M_ / BM), 256, SMEM_REQ>>>(
        xh, xl, Wh, Wl, kvr, 3, 2);
    scan1_kernel<<<dim3(NC_ / 4, B_), 256>>>(td);
    scan_carry_kernel<<<B_, 256>>>(td);
    scan2_kernel<<<dim3(NC_ / 4, B_), 256>>>(td);
    mma_gemm_kernel<<<dim3(C_ / BN, M_ / BM), 256, SMEM_REQ>>>(
        yh, yl, Woh, Wol, out, 1, -1);
}

// round 5
// speedup vs baseline: 6.4367x; 1.7673x over previous
#include <cuda_runtime.h>
#include <cuda_fp16.h>
#include <math.h>
#include <stdint.h>

#define B_  8
#define N_  16384
#define C_  256
#define M_  (B_*N_)      // 131072 rows
#define MC_ ((size_t)M_*C_)
#define L_  128          // scan chunk length
#define NC_ (N_/L_)      // 128 chunks

// ---- GEMM tiling ----
#define BM 128
#define BN 64
#define KCH 64                 // K chunk (fp16 elems)
#define NKC (C_/KCH)           // 4 chunks
#define SAS 72                 // smem row stride in halves (144B)
#define A_B (BM*SAS*2)         // 18432 B
#define B_B (BN*SAS*2)         // 9216 B
#define STAGE_B (A_B + B_B)    // 27648
#define SMEM_REQ (2*STAGE_B)   // 55296

// ---- scratch ----
__device__ float  g_k[MC_];
__device__ __half g_vr[2*MC_];          // v at 0, r at MC_
__device__ __half g_xa[MC_];            // LN(x) fp16
__device__ __half g_ya[MC_];            // y fp16
__device__ __half g_Wa[3*C_*C_];        // Wk,Wv,Wr fp16
__device__ __half g_Woa[C_*C_];         // Wo fp16
__device__ float  g_e[B_*NC_*C_];
__device__ float  g_carry[B_*NC_*C_];

// ============================================================
// helpers
// ============================================================
__device__ __forceinline__ uint32_t smem_u32(const void* p) {
    return (uint32_t)__cvta_generic_to_shared(p);
}
__device__ __forceinline__ void ldm_x4(uint32_t* r, uint32_t addr) {
    asm volatile("ldmatrix.sync.aligned.m8n8.x4.shared.b16 {%0,%1,%2,%3}, [%4];"
                 : "=r"(r[0]), "=r"(r[1]), "=r"(r[2]), "=r"(r[3]) : "r"(addr));
}
__device__ __forceinline__ void mma16816(float* c, const uint32_t* a,
                                         uint32_t b0, uint32_t b1) {
    asm volatile(
        "mma.sync.aligned.m16n8k16.row.col.f32.f16.f16.f32 "
        "{%0,%1,%2,%3}, {%4,%5,%6,%7}, {%8,%9}, {%0,%1,%2,%3};"
        : "+f"(c[0]), "+f"(c[1]), "+f"(c[2]), "+f"(c[3])
        : "r"(a[0]), "r"(a[1]), "r"(a[2]), "r"(a[3]), "r"(b0), "r"(b1));
}
__device__ __forceinline__ void cp16(uint32_t sm, const void* g) {
    asm volatile("cp.async.cg.shared.global [%0], [%1], 16;" :: "r"(sm), "l"(g));
}
__device__ __forceinline__ void cp_commit() {
    asm volatile("cp.async.commit_group;");
}
template <int N>
__device__ __forceinline__ void cp_wait() {
    asm volatile("cp.async.wait_group %0;" :: "n"(N));
}

// ============================================================
// 1) LayerNorm -> fp16
// ============================================================
__global__ __launch_bounds__(256) void ln_kernel(
    const float* __restrict__ x,
    const float* __restrict__ lnw, const float* __restrict__ lnb)
{
    int row  = blockIdx.x * 8 + (threadIdx.x >> 5);
    int lane = threadIdx.x & 31;
    int c0   = lane * 8;
    const float4* xr = reinterpret_cast<const float4*>(x + (size_t)row * C_ + c0);
    float4 f0 = xr[0], f1 = xr[1];
    float v[8] = {f0.x, f0.y, f0.z, f0.w, f1.x, f1.y, f1.z, f1.w};

    float s = 0.f, s2 = 0.f;
    #pragma unroll
    for (int j = 0; j < 8; j++) { s += v[j]; s2 += v[j] * v[j]; }
    #pragma unroll
    for (int o = 16; o > 0; o >>= 1) {
        s  += __shfl_xor_sync(0xffffffffu, s,  o);
        s2 += __shfl_xor_sync(0xffffffffu, s2, o);
    }
    float mu   = s * (1.0f / C_);
    float var  = s2 * (1.0f / C_) - mu * mu;
    float rstd = rsqrtf(var + 1e-5f);

    union { __half h[8]; uint4 u; } ha;
    #pragma unroll
    for (int j = 0; j < 8; j++) {
        float xn = (v[j] - mu) * rstd * lnw[c0 + j] + lnb[c0 + j];
        ha.h[j] = __float2half_rn(xn);
    }
    *reinterpret_cast<uint4*>(&g_xa[(size_t)row * C_ + c0]) = ha.u;
}

// ============================================================
// 2) Weight convert -> fp16
// ============================================================
__global__ __launch_bounds__(256) void wconv_kernel(
    const float* __restrict__ Wk, const float* __restrict__ Wv,
    const float* __restrict__ Wr, const float* __restrict__ Wo)
{
    int idx = blockIdx.x * 256 + threadIdx.x;
    int mat = idx >> 16, rem = idx & 65535;
    float val = (mat == 0) ? Wk[rem] : (mat == 1) ? Wv[rem]
              : (mat == 2) ? Wr[rem] : Wo[rem];
    __half h = __float2half_rn(val);
    if (mat < 3) g_Wa[idx] = h;
    else         g_Woa[rem] = h;
}

// ============================================================
// 3) fp16 mma.sync GEMM, cp.async double-buffered.
//    Block 128x64, K=256 in 64-chunks, 8 warps (4m x 2n).
//    z==0 -> fp32 out (outF); z>=1 -> fp16 out (outH+(z-1)*MC_),
//    sigmoid applied when z==sig_z.
// ============================================================
__global__ void __launch_bounds__(256, 2) mma_gemm_kernel(
    const __half* __restrict__ A, const __half* __restrict__ W,
    float* __restrict__ outF, __half* __restrict__ outH,
    int nz, int sig_z)
{
    extern __shared__ __half sm[];
    uint32_t sbase = smem_u32(sm);

    int zc = blockIdx.x;
    int z  = zc % nz;
    int ny = zc / nz;
    size_t m0 = (size_t)blockIdx.y * BM;
    int n0 = ny * BN;
    const __half* w = W + (size_t)z * C_ * C_;

    int tid = threadIdx.x;
    int warp = tid >> 5, lane = tid & 31;
    int wm = (warp & 3) * 32;
    int wn = (warp >> 2) * 32;
    int gID = lane >> 2, tig = lane & 3;

    float acc[2][4][4];
    #pragma unroll
    for (int i = 0; i < 2; i++)
        #pragma unroll
        for (int j = 0; j < 4; j++)
            #pragma unroll
            for (int q = 0; q < 4; q++) acc[i][j][q] = 0.f;

    int arow  = lane & 15;
    int acolo = (lane >> 4) << 3;
    int q4 = lane >> 3;
    int brow_in = (lane & 7) + ((q4 >> 1) << 3);
    int bcolo = (q4 & 1) << 3;

    auto load_chunk = [&](int kc, int stg) {
        uint32_t base = sbase + stg * STAGE_B;
        int k0 = kc * KCH;
        #pragma unroll
        for (int it = 0; it < 4; it++) {            // A: 1024 vec16
            int v = it * 256 + tid;
            int r = v >> 3, cv = v & 7;
            cp16(base + r * (SAS * 2) + cv * 16,
                 A + (m0 + r) * C_ + k0 + cv * 8);
        }
        #pragma unroll
        for (int it = 0; it < 2; it++) {            // B: 512 vec16
            int v = it * 256 + tid;
            int r = v >> 3, cv = v & 7;
            cp16(base + A_B + r * (SAS * 2) + cv * 16,
                 w + (size_t)(n0 + r) * C_ + k0 + cv * 8);
        }
        cp_commit();
    };

    load_chunk(0, 0);

    for (int kc = 0; kc < NKC; kc++) {
        cp_wait<0>();
        __syncthreads();
        if (kc + 1 < NKC) load_chunk(kc + 1, (kc + 1) & 1);

        uint32_t base = sbase + (kc & 1) * STAGE_B;
        uint32_t aB = base, bB = base + A_B;

        #pragma unroll
        for (int ks = 0; ks < KCH / 16; ks++) {
            int kk = ks * 16;
            uint32_t a[2][4], b[2][4];
            #pragma unroll
            for (int i = 0; i < 2; i++)
                ldm_x4(a[i], aB + (wm + i * 16 + arow) * (SAS * 2) + (kk + acolo) * 2);
            #pragma unroll
            for (int p = 0; p < 2; p++)
                ldm_x4(b[p], bB + (wn + p * 16 + brow_in) * (SAS * 2) + (kk + bcolo) * 2);
            #pragma unroll
            for (int i = 0; i < 2; i++)
                #pragma unroll
                for (int j = 0; j < 4; j++) {
                    int p = j >> 1, o = (j & 1) * 2;
                    mma16816(acc[i][j], a[i], b[p][o], b[p][o + 1]);
                }
        }
    }

    bool sig = (z == sig_z);
    if (z == 0) {
        #pragma unroll
        for (int i = 0; i < 2; i++) {
            size_t row0 = m0 + wm + i * 16 + gID;
            #pragma unroll
            for (int j = 0; j < 4; j++) {
                int col = n0 + wn + j * 8 + tig * 2;
                *reinterpret_cast<float2*>(&outF[row0 * C_ + col]) =
                    make_float2(acc[i][j][0], acc[i][j][1]);
                *reinterpret_cast<float2*>(&outF[(row0 + 8) * C_ + col]) =
                    make_float2(acc[i][j][2], acc[i][j][3]);
            }
        }
    } else {
        __half* oh = outH + (size_t)(z - 1) * MC_;
        #pragma unroll
        for (int i = 0; i < 2; i++) {
            size_t row0 = m0 + wm + i * 16 + gID;
            #pragma unroll
            for (int j = 0; j < 4; j++) {
                int col = n0 + wn + j * 8 + tig * 2;
                float v0 = acc[i][j][0], v1 = acc[i][j][1];
                float v2 = acc[i][j][2], v3 = acc[i][j][3];
                if (sig) {
                    v0 = 1.0f / (1.0f + __expf(-v0));
                    v1 = 1.0f / (1.0f + __expf(-v1));
                    v2 = 1.0f / (1.0f + __expf(-v2));
                    v3 = 1.0f / (1.0f + __expf(-v3));
                }
                *reinterpret_cast<__half2*>(&oh[row0 * C_ + col]) =
                    __floats2half2_rn(v0, v1);
                *reinterpret_cast<__half2*>(&oh[(row0 + 8) * C_ + col]) =
                    __floats2half2_rn(v2, v3);
            }
        }
    }
}

// ============================================================
// 4) Scan pass 1 (float4): chunk-end values.  grid (NC_/4, B_)
// ============================================================
__global__ __launch_bounds__(256) void scan1_kernel(const float* __restrict__ td) {
    int sub = threadIdx.x >> 6, t = threadIdx.x & 63;
    int j = blockIdx.x * 4 + sub, b = blockIdx.y;
    int c0 = t * 4;
    float4 tdv = *reinterpret_cast<const float4*>(td + c0);
    float dx = expf(-fmaxf(tdv.x, 0.f)), dy = expf(-fmaxf(tdv.y, 0.f));
    float dz = expf(-fmaxf(tdv.z, 0.f)), dw = expf(-fmaxf(tdv.w, 0.f));
    const float4* kp = reinterpret_cast<const float4*>(
        g_k + ((size_t)(b * N_ + j * L_)) * C_) + t;
    float4 s = make_float4(0.f, 0.f, 0.f, 0.f);
    #pragma unroll 8
    for (int i = 0; i < L_; i++) {
        float4 kv = kp[(size_t)i * (C_ / 4)];
        s.x = fmaf(s.x, dx, kv.x); s.y = fmaf(s.y, dy, kv.y);
        s.z = fmaf(s.z, dz, kv.z); s.w = fmaf(s.w, dw, kv.w);
    }
    reinterpret_cast<float4*>(g_e + (b * NC_ + j) * C_)[t] = s;
}

// ============================================================
// 5) Carry propagation, batched independent loads
// ============================================================
__global__ __launch_bounds__(256) void scan_carry_kernel(const float* __restrict__ td) {
    int b = blockIdx.x, c = threadIdx.x;
    float r  = fmaxf(td[c], 0.f);
    float dL = expf(-r * (float)L_);
    float cy = 0.f;
    for (int jb = 0; jb < NC_; jb += 8) {
        float e[8];
        #pragma unroll
        for (int u = 0; u < 8; u++) e[u] = g_e[(b * NC_ + jb + u) * C_ + c];
        #pragma unroll
        for (int u = 0; u < 8; u++) {
            g_carry[(b * NC_ + jb + u) * C_ + c] = cy;
            cy = fmaf(dL, cy, e[u]);
        }
    }
}

// ============================================================
// 6) Scan pass 2 + y = r*(s+v) -> fp16.  grid (NC_/4, B_)
// ============================================================
__global__ __launch_bounds__(256) void scan2_kernel(const float* __restrict__ td) {
    int sub = threadIdx.x >> 6, t = threadIdx.x & 63;
    int j = blockIdx.x * 4 + sub, b = blockIdx.y;
    int c0 = t * 4;
    float4 tdv = *reinterpret_cast<const float4*>(td + c0);
    float dx = expf(-fmaxf(tdv.x, 0.f)), dy = expf(-fmaxf(tdv.y, 0.f));
    float dz = expf(-fmaxf(tdv.z, 0.f)), dw = expf(-fmaxf(tdv.w, 0.f));
    size_t base = ((size_t)(b * N_ + j * L_)) * C_ + c0;
    float4 s = reinterpret_cast<const float4*>(g_carry + (b * NC_ + j) * C_)[t];
    #pragma unroll 4
    for (int i = 0; i < L_; i++) {
        size_t off = base + (size_t)i * C_;
        float4 kv = *reinterpret_cast<const float4*>(g_k + off);
        __half2 v01 = *reinterpret_cast<const __half2*>(&g_vr[off]);
        __half2 v23 = *reinterpret_cast<const __half2*>(&g_vr[off + 2]);
        __half2 r01 = *reinterpret_cast<const __half2*>(&g_vr[MC_ + off]);
        __half2 r23 = *reinterpret_cast<const __half2*>(&g_vr[MC_ + off + 2]);
        s.x = fmaf(s.x, dx, kv.x); s.y = fmaf(s.y, dy, kv.y);
        s.z = fmaf(s.z, dz, kv.z); s.w = fmaf(s.w, dw, kv.w);
        float y0 = __low2float(r01)  * (s.x + __low2float(v01));
        float y1 = __high2float(r01) * (s.y + __high2float(v01));
        float y2 = __low2float(r23)  * (s.z + __low2float(v23));
        float y3 = __high2float(r23) * (s.w + __high2float(v23));
        union { __half2 h2[2]; uint2 u; } Y;
        Y.h2[0] = __floats2half2_rn(y0, y1);
        Y.h2[1] = __floats2half2_rn(y2, y3);
        *reinterpret_cast<uint2*>(&g_ya[off]) = Y.u;
    }
}

// ============================================================
// launch
// ============================================================
extern "C" void kernel_launch(void* const* d_in, const int* in_sizes, int n_in,
                              void* d_out, int out_size) {
    const float* x   = (const float*)d_in[0];
    const float* td  = (const float*)d_in[1];
    const float* Wk  = (const float*)d_in[2];
    const float* Wv  = (const float*)d_in[3];
    const float* Wr  = (const float*)d_in[4];
    const float* Wo  = (const float*)d_in[5];
    const float* lnw = (const float*)d_in[6];
    const float* lnb = (const float*)d_in[7];
    float* out = (float*)d_out;

    __half *xa, *ya, *Wa, *Woa, *vr;
    float *k;
    cudaGetSymbolAddress((void**)&xa,  g_xa);
    cudaGetSymbolAddress((void**)&ya,  g_ya);
    cudaGetSymbolAddress((void**)&Wa,  g_Wa);
    cudaGetSymbolAddress((void**)&Woa, g_Woa);
    cudaGetSymbolAddress((void**)&vr,  g_vr);
    cudaGetSymbolAddress((void**)&k,   g_k);

    cudaFuncSetAttribute(mma_gemm_kernel,
                         cudaFuncAttributeMaxDynamicSharedMemorySize, SMEM_REQ);

    ln_kernel<<<M_ / 8, 256>>>(x, lnw, lnb);
    wconv_kernel<<<1024, 256>>>(Wk, Wv, Wr, Wo);
    // z=0 -> k (fp32), z=1 -> v (fp16), z=2 -> sigmoid r (fp16)
    mma_gemm_kernel<<<dim3((C_ / BN) * 3, M_ / BM), 256, SMEM_REQ>>>(
        xa, Wa, k, vr, 3, 2);
    scan1_kernel<<<dim3(NC_ / 4, B_), 256>>>(td);
    scan_carry_kernel<<<B_, 256>>>(td);
    scan2_kernel<<<dim3(NC_ / 4, B_), 256>>>(td);
    // output GEMM: z=0 -> fp32 out
    mma_gemm_kernel<<<dim3(C_ / BN, M_ / BM), 256, SMEM_REQ>>>(
        ya, Woa, out, nullptr, 1, -1);
}